// round 14
// baseline (speedup 1.0000x reference)
#include <cuda_runtime.h>
#include <math.h>

// Problem constants (fixed by the reference)
#define NV 200
#define NE 512
#define NH 512
#define NT 24
#define NB 1024
#define NS 128
#define BIGF 10000.0f
#define FPSCALE 1048576.0f   // 2^20 fixed-point scale for deterministic reduce
#define KC 8                 // split-K chunks in hidden GEMM
#define KCH 64               // k per chunk
#define NCTA 128
#define NTHR 256

// Scratch (no cudaMalloc allowed). All zero-init; counters reset at end of
// every launch by the final CTA so graph replays start clean.
__device__ __align__(16) float g_w1t[NE * NH];        // w1 transposed [e][j]
__device__ __align__(16) float g_part[KC * NV * NH];  // split-K partials
__device__ __align__(16) float g_tab[NV * NT];        // log scores (BIG baked into [0][0])
__device__ __align__(16) float g_etab[NV * NT];       // exp(score - rowmax)
__device__ __align__(16) float g_roff[NV];            // rowmax per vocab row
__device__ unsigned long long g_acc;                  // fixed-point llh accumulator
__device__ unsigned int       g_ticket;               // last-block ticket
__device__ unsigned int       g_bar[4];               // grid-sync counters

__device__ __forceinline__ unsigned int smem_addr(const void* p) {
    return (unsigned int)__cvta_generic_to_shared(p);
}

__device__ __forceinline__ void grid_sync(int k) {
    __syncthreads();
    if (threadIdx.x == 0) {
        __threadfence();
        atomicAdd(&g_bar[k], 1u);
        volatile unsigned int* vp = (volatile unsigned int*)&g_bar[k];
        while (*vp < NCTA) { }
        __threadfence();
    }
    __syncthreads();
}

// ---------------------------------------------------------------------------
// ONE persistent kernel: transpose -> hidden GEMM -> score tables -> CRF scan
// grid 128 CTAs x 256 threads (all resident on 148 SMs -> spin sync is safe).
// ---------------------------------------------------------------------------
__global__ __launch_bounds__(NTHR, 1)
void k_fused(const int*   __restrict__ seqs,
             const int*   __restrict__ labs,
             const float* __restrict__ emb,
             const float* __restrict__ w1,
             const float* __restrict__ b1,
             const float* __restrict__ w2,
             const float* __restrict__ b2,
             const float* __restrict__ st,
             const float* __restrict__ et,
             const float* __restrict__ trans,
             float*       __restrict__ out) {
    __shared__ __align__(16) float tile[32][33];     // phase 1
    __shared__ __align__(16) float setb[KCH * 8];    // phase 2
    __shared__ __align__(16) float sh[NH];           // phase 3
    __shared__ float sS[NT];
    __shared__ __align__(16) float setab[NV * NT];   // phase 4 tables
    __shared__ __align__(16) float sroff[NV];
    __shared__ __align__(16) float strans[NT * NT];
    __shared__ __align__(16) int   sseq[8][NS];
    __shared__ float sst[NT], setr[NT];
    __shared__ float snum[8], sden[8];
    __shared__ __align__(16) float pbuf[4][2][2][32]; // [warp][seq][buf][lane]

    const int tid = threadIdx.x;
    const int cta = blockIdx.x;
    const int wid = tid >> 5;
    const int lane = tid & 31;

    // ---- Phase 1: transpose w1 (256 tiles of 32x32, 2 per CTA) ----
    {
        int tx = tid & 31, ty = tid >> 5;   // 32 x 8
        for (int u = cta; u < 256; u += NCTA) {
            int bx = u & 15, by = u >> 4;
            int x = bx * 32 + tx, y = by * 32 + ty;
#pragma unroll
            for (int i = 0; i < 32; i += 8)
                tile[ty + i][tx] = w1[(size_t)(y + i) * NE + x];
            __syncthreads();
            x = by * 32 + tx; y = bx * 32 + ty;
#pragma unroll
            for (int i = 0; i < 32; i += 8)
                g_w1t[(size_t)(y + i) * NH + x] = tile[tx][ty + i];
            __syncthreads();
        }
    }
    grid_sync(0);

    // ---- Phase 2: split-K hidden GEMM partials (200 units, <=2 per CTA) ----
    for (int u = cta; u < 200; u += NCTA) {
        int v0 = (u % 25) * 8;
        int kb = u / 25;
        int k0 = kb * KCH;
        for (int i = tid; i < KCH * 8; i += NTHR) {
            int vi = i >> 6, kk = i & 63;
            setb[kk * 8 + vi] = emb[(size_t)(v0 + vi) * NE + k0 + kk];
        }
        __syncthreads();

        int j4 = tid & 127;          // float4 column
        int half = tid >> 7;         // v rows 0-3 or 4-7
        float4 a0 = {0,0,0,0}, a1 = {0,0,0,0}, a2 = {0,0,0,0}, a3 = {0,0,0,0};
        const float4* wp = reinterpret_cast<const float4*>(g_w1t + (size_t)k0 * NH) + j4;
        const float4* eb = reinterpret_cast<const float4*>(setb);
#pragma unroll 4
        for (int kk = 0; kk < KCH; kk++) {
            float4 w = wp[kk * (NH / 4)];
            float4 e = eb[kk * 2 + half];
            a0.x = fmaf(e.x, w.x, a0.x); a0.y = fmaf(e.x, w.y, a0.y);
            a0.z = fmaf(e.x, w.z, a0.z); a0.w = fmaf(e.x, w.w, a0.w);
            a1.x = fmaf(e.y, w.x, a1.x); a1.y = fmaf(e.y, w.y, a1.y);
            a1.z = fmaf(e.y, w.z, a1.z); a1.w = fmaf(e.y, w.w, a1.w);
            a2.x = fmaf(e.z, w.x, a2.x); a2.y = fmaf(e.z, w.y, a2.y);
            a2.z = fmaf(e.z, w.z, a2.z); a2.w = fmaf(e.z, w.w, a2.w);
            a3.x = fmaf(e.w, w.x, a3.x); a3.y = fmaf(e.w, w.y, a3.y);
            a3.z = fmaf(e.w, w.z, a3.z); a3.w = fmaf(e.w, w.w, a3.w);
        }
        float* outp = g_part + (size_t)kb * (NV * NH);
        int vb = v0 + half * 4;
        reinterpret_cast<float4*>(outp + (size_t)(vb + 0) * NH)[j4] = a0;
        reinterpret_cast<float4*>(outp + (size_t)(vb + 1) * NH)[j4] = a1;
        reinterpret_cast<float4*>(outp + (size_t)(vb + 2) * NH)[j4] = a2;
        reinterpret_cast<float4*>(outp + (size_t)(vb + 3) * NH)[j4] = a3;
        __syncthreads();
    }
    grid_sync(1);

    // ---- Phase 3: score tables (200 v rows, <=2 per CTA) ----
    for (int v = cta; v < NV; v += NCTA) {
        for (int j = tid; j < NH; j += NTHR) {
            float s = b1[j];
#pragma unroll
            for (int p = 0; p < KC; p++) s += g_part[p * (NV * NH) + (size_t)v * NH + j];
            sh[j] = fmaxf(s, 0.0f);
        }
        __syncthreads();
        for (int tt = wid; tt < NT; tt += 8) {
            const float* w = w2 + tt * NH;
            float acc = 0.0f;
            for (int j = lane; j < NH; j += 32) acc = fmaf(sh[j], w[j], acc);
#pragma unroll
            for (int o = 16; o; o >>= 1) acc += __shfl_down_sync(0xffffffffu, acc, o);
            if (lane == 0) {
                float sc = fmaxf(acc + b2[tt], 0.0f);
                if (v == 0 && tt == 0) sc += BIGF;   // pad bonus baked in
                sS[tt] = sc;
            }
        }
        __syncthreads();
        if (tid < NT) {
            float sc = sS[tid];
            float rm = sS[0];
#pragma unroll
            for (int i = 1; i < NT; i++) rm = fmaxf(rm, sS[i]);
            g_tab[v * NT + tid]  = sc;
            g_etab[v * NT + tid] = __expf(sc - rm);
            if (tid == 0) g_roff[v] = rm;
        }
        __syncthreads();
    }
    grid_sync(2);

    // ---- Phase 4 prologue: stage tables + this CTA's 8 sequences in smem ----
    {
        float4*       d2 = reinterpret_cast<float4*>(setab);
        const float4* s2 = reinterpret_cast<const float4*>(g_etab);
        for (int i = tid; i < (NV * NT) / 4; i += NTHR) d2[i] = s2[i];
        for (int i = tid; i < NV / 4; i += NTHR)
            reinterpret_cast<float4*>(sroff)[i] = reinterpret_cast<const float4*>(g_roff)[i];
        for (int i = tid; i < (NT * NT) / 4; i += NTHR)
            reinterpret_cast<float4*>(strans)[i] = reinterpret_cast<const float4*>(trans)[i];
        if (tid < NT) { sst[tid] = st[tid]; setr[tid] = et[tid]; }
        const int4* sq = reinterpret_cast<const int4*>(seqs + cta * 8 * NS);
        for (int i = tid; i < (8 * NS) / 4; i += NTHR)
            reinterpret_cast<int4*>(&sseq[0][0])[i] = sq[i];
    }
    __syncthreads();

    if (wid < 4) {
        // ---- Scan warps: 2 interleaved sequences per warp, f32x2 math ----
        const int s0 = 2 * wid, s1 = 2 * wid + 1;
        const int* seqA = sseq[s0];
        const int* seqB = sseq[s1];
        const bool act = lane < NT;
        const int  tc  = act ? lane : 0;

        // packed exp(transitions) column pairs for this lane (one-time)
        unsigned long long Epk[12];
#pragma unroll
        for (int p = 0; p < 12; p++) {
            float e0 = act ? __expf(strans[(2 * p) * NT + tc]) : 0.0f;
            float e1 = act ? __expf(strans[(2 * p + 1) * NT + tc]) : 0.0f;
            asm("mov.b64 %0, {%1,%2};" : "=l"(Epk[p]) : "f"(e0), "f"(e1));
        }

        float pA = act ? __expf(sst[tc]) * setab[seqA[0] * NT + tc] : 0.0f;
        float pB = act ? __expf(sst[tc]) * setab[seqB[0] * NT + tc] : 0.0f;
        float cA = 0.0f, cB = 0.0f;
        pbuf[wid][0][0][lane] = pA;
        pbuf[wid][1][0][lane] = pB;
        __syncwarp();

        const unsigned int bA0 = smem_addr(&pbuf[wid][0][0][0]);
        const unsigned int bA1 = bA0 + 128;
        const unsigned int bB0 = smem_addr(&pbuf[wid][1][0][0]);
        const unsigned int bB1 = bB0 + 128;

        auto stepf = [&](unsigned int rb, int sv, float& p, float& c, bool renorm) {
            unsigned long long a0,a1,a2,a3,a4,a5,a6,a7,a8,a9,aA,aB;
            asm volatile("ld.shared.v2.b64 {%0,%1},[%2];" : "=l"(a0),"=l"(a1) : "r"(rb));
            asm volatile("ld.shared.v2.b64 {%0,%1},[%2];" : "=l"(a2),"=l"(a3) : "r"(rb+16u));
            asm volatile("ld.shared.v2.b64 {%0,%1},[%2];" : "=l"(a4),"=l"(a5) : "r"(rb+32u));
            asm volatile("ld.shared.v2.b64 {%0,%1},[%2];" : "=l"(a6),"=l"(a7) : "r"(rb+48u));
            asm volatile("ld.shared.v2.b64 {%0,%1},[%2];" : "=l"(a8),"=l"(a9) : "r"(rb+64u));
            asm volatile("ld.shared.v2.b64 {%0,%1},[%2];" : "=l"(aA),"=l"(aB) : "r"(rb+80u));
            unsigned long long q0,q1,q2;
            asm("mul.rn.f32x2 %0,%1,%2;"    : "=l"(q0) : "l"(a0), "l"(Epk[0]));
            asm("mul.rn.f32x2 %0,%1,%2;"    : "=l"(q1) : "l"(a1), "l"(Epk[1]));
            asm("mul.rn.f32x2 %0,%1,%2;"    : "=l"(q2) : "l"(a2), "l"(Epk[2]));
            asm("fma.rn.f32x2 %0,%1,%2,%3;" : "=l"(q0) : "l"(a3), "l"(Epk[3]), "l"(q0));
            asm("fma.rn.f32x2 %0,%1,%2,%3;" : "=l"(q1) : "l"(a4), "l"(Epk[4]), "l"(q1));
            asm("fma.rn.f32x2 %0,%1,%2,%3;" : "=l"(q2) : "l"(a5), "l"(Epk[5]), "l"(q2));
            asm("fma.rn.f32x2 %0,%1,%2,%3;" : "=l"(q0) : "l"(a6), "l"(Epk[6]), "l"(q0));
            asm("fma.rn.f32x2 %0,%1,%2,%3;" : "=l"(q1) : "l"(a7), "l"(Epk[7]), "l"(q1));
            asm("fma.rn.f32x2 %0,%1,%2,%3;" : "=l"(q2) : "l"(a8), "l"(Epk[8]), "l"(q2));
            asm("fma.rn.f32x2 %0,%1,%2,%3;" : "=l"(q0) : "l"(a9), "l"(Epk[9]), "l"(q0));
            asm("fma.rn.f32x2 %0,%1,%2,%3;" : "=l"(q1) : "l"(aA), "l"(Epk[10]), "l"(q1));
            asm("fma.rn.f32x2 %0,%1,%2,%3;" : "=l"(q2) : "l"(aB), "l"(Epk[11]), "l"(q2));
            asm("add.rn.f32x2 %0,%1,%2;" : "=l"(q0) : "l"(q0), "l"(q1));
            asm("add.rn.f32x2 %0,%1,%2;" : "=l"(q0) : "l"(q0), "l"(q2));
            float lo, hi;
            asm("mov.b64 {%0,%1}, %2;" : "=f"(lo), "=f"(hi) : "l"(q0));
            float q = lo + hi;
            float e = setab[sv * NT + tc];
            p = q * e;
            if (renorm) {
                unsigned long long t0,t1,t2;
                asm("add.rn.f32x2 %0,%1,%2;" : "=l"(t0) : "l"(a0), "l"(a1));
                asm("add.rn.f32x2 %0,%1,%2;" : "=l"(t1) : "l"(a2), "l"(a3));
                asm("add.rn.f32x2 %0,%1,%2;" : "=l"(t2) : "l"(a4), "l"(a5));
                asm("add.rn.f32x2 %0,%1,%2;" : "=l"(t0) : "l"(t0), "l"(t1));
                asm("add.rn.f32x2 %0,%1,%2;" : "=l"(t1) : "l"(a6), "l"(a7));
                asm("add.rn.f32x2 %0,%1,%2;" : "=l"(t2) : "l"(t2), "l"(t1));
                asm("add.rn.f32x2 %0,%1,%2;" : "=l"(t1) : "l"(a8), "l"(a9));
                asm("add.rn.f32x2 %0,%1,%2;" : "=l"(t0) : "l"(t0), "l"(t1));
                asm("add.rn.f32x2 %0,%1,%2;" : "=l"(t1) : "l"(aA), "l"(aB));
                asm("add.rn.f32x2 %0,%1,%2;" : "=l"(t2) : "l"(t2), "l"(t1));
                asm("add.rn.f32x2 %0,%1,%2;" : "=l"(t0) : "l"(t0), "l"(t2));
                float slo, shi;
                asm("mov.b64 {%0,%1}, %2;" : "=f"(slo), "=f"(shi) : "l"(t0));
                float ssum = slo + shi;
                p *= __fdividef(1.0f, ssum);
                c += __logf(ssum);
            }
        };

#pragma unroll 1
        for (int s = 1; s < NS; s++) {
            int par = s & 1;                 // write buffer; read the other
            bool rn = (s & 7) == 0;
            int svA = seqA[s], svB = seqB[s];
            stepf(par ? bA0 : bA1, svA, pA, cA, rn);
            pbuf[wid][0][par][lane] = pA;
            stepf(par ? bB0 : bB1, svB, pB, cB, rn);
            pbuf[wid][1][par][lane] = pB;
            __syncwarp();
        }

        // den_part = c + log( sum_t p[t]*exp(end[t]) )   (roff sum folded into num)
        float eeE = act ? __expf(setr[tc]) : 0.0f;
        float vA = pA * eeE, vB = pB * eeE;
#pragma unroll
        for (int o = 16; o; o >>= 1) {
            vA += __shfl_xor_sync(0xffffffffu, vA, o);
            vB += __shfl_xor_sync(0xffffffffu, vB, o);
        }
        if (lane == 0) {
            sden[s0] = cA + __logf(vA);
            sden[s1] = cB + __logf(vB);
        }
    } else {
        // ---- Numerator warps (4-7): gold path + roff sums for 2 seqs each ----
        int wi = wid - 4;
#pragma unroll 1
        for (int j = 0; j < 2; j++) {
            int slot = 2 * wi + j;
            int b = cta * 8 + slot;
            const int* seq = sseq[slot];
            const int* lab = labs + b * NS;
            float nacc = 0.0f, racc = 0.0f;
            for (int s = lane; s < NS; s += 32) {
                int sv = seq[s], ls = lab[s];
                nacc += g_tab[sv * NT + ls];
                racc += sroff[sv];
                if (s + 1 < NS) nacc += strans[ls * NT + lab[s + 1]];
            }
#pragma unroll
            for (int o = 16; o; o >>= 1) {
                nacc += __shfl_xor_sync(0xffffffffu, nacc, o);
                racc += __shfl_xor_sync(0xffffffffu, racc, o);
            }
            if (lane == 0)
                snum[slot] = nacc + sst[lab[0]] + setr[lab[NS - 1]] - racc;
        }
    }
    __syncthreads();

    // ---- Fused deterministic reduce + final-CTA output + counter reset ----
    if (tid == 0) {
        float bs = 0.0f;
#pragma unroll
        for (int w = 0; w < 8; w++) bs += snum[w] - sden[w];
        long long q = __float2ll_rn(bs * FPSCALE);
        atomicAdd(&g_acc, (unsigned long long)q);
        __threadfence();
        unsigned int done = atomicAdd(&g_ticket, 1u);
        if (done == NCTA - 1) {
            unsigned long long tot = atomicAdd(&g_acc, 0ULL);
            double mean = (double)(long long)tot / ((double)FPSCALE * (double)NB);
            out[0] = (float)(-mean);
            // reset for the next graph replay (all CTAs are past all barriers)
            g_acc = 0ULL;
            g_ticket = 0u;
            g_bar[0] = 0u; g_bar[1] = 0u; g_bar[2] = 0u; g_bar[3] = 0u;
            __threadfence();
        }
    }
}

// ---------------------------------------------------------------------------
extern "C" void kernel_launch(void* const* d_in, const int* in_sizes, int n_in,
                              void* d_out, int out_size) {
    const int*   sequences   = (const int*)  d_in[0];
    const int*   labels      = (const int*)  d_in[1];
    // d_in[2] = true_lengths (unused by the reference forward)
    const float* emb         = (const float*)d_in[3];
    const float* w1          = (const float*)d_in[4];
    const float* b1          = (const float*)d_in[5];
    const float* w2          = (const float*)d_in[6];
    const float* b2          = (const float*)d_in[7];
    const float* start_trans = (const float*)d_in[8];
    const float* end_trans   = (const float*)d_in[9];
    const float* transitions = (const float*)d_in[10];
    float* out = (float*)d_out;

    k_fused<<<NCTA, NTHR>>>(sequences, labels, emb, w1, b1, w2, b2,
                            start_trans, end_trans, transitions, out);
}

// round 15
// speedup vs baseline: 1.0430x; 1.0430x over previous
#include <cuda_runtime.h>
#include <math.h>

// Problem constants (fixed by the reference)
#define NV 200
#define NE 512
#define NH 512
#define NT 24
#define NB 1024
#define NS 128
#define BIGF 10000.0f
#define FPSCALE 1048576.0f   // 2^20 fixed-point scale for deterministic reduce
#define KC 8                 // split-K chunks in k_hidden
#define KCH (NE / KC)        // 64 k per chunk

// Scratch (no cudaMalloc allowed)
__device__ float g_w1t[NE * NH];          // w1 transposed: [e][j]
__device__ float g_part[KC * NV * NH];    // split-K partial sums
__device__ float g_tab[NV * NT];          // log-domain scores (BIG baked into [0][0])
__device__ float g_etab[NV * NT];         // exp(score - rowmax)
__device__ float g_roff[NV];              // rowmax per vocab row
__device__ unsigned long long g_acc;      // fixed-point llh accumulator
__device__ unsigned int       g_ticket;   // last-block ticket

// ---------------------------------------------------------------------------
// Kernel 0: transpose w1 (512x512) -> g_w1t, and reset reduce counters.
// grid (16,16), block (32,8).
// ---------------------------------------------------------------------------
__global__ void k_transpose(const float* __restrict__ w1) {
    if (blockIdx.x == 0 && blockIdx.y == 0 && threadIdx.x == 0 && threadIdx.y == 0) {
        g_acc = 0ULL;
        g_ticket = 0u;
    }
    __shared__ float tile[32][33];
    int x = blockIdx.x * 32 + threadIdx.x;
    int y = blockIdx.y * 32 + threadIdx.y;
#pragma unroll
    for (int i = 0; i < 32; i += 8)
        tile[threadIdx.y + i][threadIdx.x] = w1[(size_t)(y + i) * NE + x];
    __syncthreads();
    x = blockIdx.y * 32 + threadIdx.x;
    y = blockIdx.x * 32 + threadIdx.y;
#pragma unroll
    for (int i = 0; i < 32; i += 8)
        g_w1t[(size_t)(y + i) * NH + x] = tile[threadIdx.x][threadIdx.y + i];
}

// ---------------------------------------------------------------------------
// Kernel 1: split-K hidden GEMM partials.
// grid (NV/8 = 25, KC = 8), block 128. Thread owns 4 j (float4) x 8 v accs.
// ---------------------------------------------------------------------------
__global__ void k_hidden(const float* __restrict__ emb) {
    __shared__ float setb[KCH * 8];   // emb tile transposed: [kk][vi]
    const int tid = threadIdx.x;
    const int v0  = blockIdx.x * 8;
    const int k0  = blockIdx.y * KCH;

    for (int i = tid; i < KCH * 8; i += 128) {
        int vi = i >> 6, kk = i & (KCH - 1);
        setb[kk * 8 + vi] = emb[(size_t)(v0 + vi) * NE + k0 + kk];
    }
    __syncthreads();

    float4 acc[8];
#pragma unroll
    for (int i = 0; i < 8; i++) acc[i] = make_float4(0.f, 0.f, 0.f, 0.f);

    const float4* wp = reinterpret_cast<const float4*>(g_w1t + (size_t)k0 * NH) + tid;
#pragma unroll 4
    for (int kk = 0; kk < KCH; kk++) {
        float4 w  = wp[kk * (NH / 4)];
        float4 e0 = *reinterpret_cast<const float4*>(&setb[kk * 8]);
        float4 e1 = *reinterpret_cast<const float4*>(&setb[kk * 8 + 4]);
        float ev[8] = {e0.x, e0.y, e0.z, e0.w, e1.x, e1.y, e1.z, e1.w};
#pragma unroll
        for (int vi = 0; vi < 8; vi++) {
            acc[vi].x = fmaf(ev[vi], w.x, acc[vi].x);
            acc[vi].y = fmaf(ev[vi], w.y, acc[vi].y);
            acc[vi].z = fmaf(ev[vi], w.z, acc[vi].z);
            acc[vi].w = fmaf(ev[vi], w.w, acc[vi].w);
        }
    }

    float* outp = g_part + (size_t)blockIdx.y * (NV * NH);
#pragma unroll
    for (int vi = 0; vi < 8; vi++)
        reinterpret_cast<float4*>(outp + (size_t)(v0 + vi) * NH)[tid] = acc[vi];
}

// ---------------------------------------------------------------------------
// Kernel 2: combine partials (+b1, relu) into shared, then score table +
// exp-emission table + row offsets. grid (NV), block 768 (24 warps).
// ---------------------------------------------------------------------------
__global__ void k_scores(const float* __restrict__ b1,
                         const float* __restrict__ w2,
                         const float* __restrict__ b2) {
    __shared__ float sh[NH];
    __shared__ float sS[NT];
    const int v   = blockIdx.x;
    const int tid = threadIdx.x;

    if (tid < NH) {
        float s = b1[tid];
#pragma unroll
        for (int p = 0; p < KC; p++) s += g_part[p * (NV * NH) + (size_t)v * NH + tid];
        sh[tid] = fmaxf(s, 0.0f);
    }
    __syncthreads();

    const int wid  = tid >> 5;
    const int lane = tid & 31;
    {
        const float* w = w2 + wid * NH;
        float acc = 0.0f;
        for (int j = lane; j < NH; j += 32) acc = fmaf(sh[j], w[j], acc);
#pragma unroll
        for (int o = 16; o; o >>= 1) acc += __shfl_down_sync(0xffffffffu, acc, o);
        if (lane == 0) {
            float sc = fmaxf(acc + b2[wid], 0.0f);
            if (v == 0 && wid == 0) sc += BIGF;   // pad bonus baked in
            sS[wid] = sc;
        }
    }
    __syncthreads();
    if (tid < NT) {
        int tt = tid;
        float sc = sS[tt];
        float rm = sS[0];
#pragma unroll
        for (int i = 1; i < NT; i++) rm = fmaxf(rm, sS[i]);
        g_tab[v * NT + tt]  = sc;
        g_etab[v * NT + tt] = __expf(sc - rm);
        if (tt == 0) g_roff[v] = rm;
    }
}

// ---------------------------------------------------------------------------
// Kernel 3: scaled CRF forward + gold score + fused reduce.
// TWO interleaved sequences per warp (ILP-2 hides the LDS/sync latency chain).
// grid (B/16 = 64), block 256; each of 8 warps owns sequences 2w and 2w+1.
// Cross-lane alpha broadcast stays in double-buffered shared memory; one
// __syncwarp per time step covers both sequences' stores.
// ---------------------------------------------------------------------------
__global__ void k_crf(const int*   __restrict__ seqs,
                      const int*   __restrict__ labs,
                      const float* __restrict__ st,
                      const float* __restrict__ et,
                      const float* __restrict__ trans,
                      float*       __restrict__ out) {
    __shared__ float stab[NV * NT];     // log scores (numerator lookups)
    __shared__ float setab[NV * NT];    // exp-emission table
    __shared__ float sroff[NV];
    __shared__ float strans[NT * NT];
    __shared__ int   sseq[16][NS];
    __shared__ float sst[NT], setr[NT];
    __shared__ float sll[16];
    __shared__ __align__(16) float pbuf[8][2][2][32];  // [warp][seq][buf][lane]

    const int tid = threadIdx.x;
    // vectorized prologue table loads
    {
        float4*       d1 = reinterpret_cast<float4*>(stab);
        const float4* s1 = reinterpret_cast<const float4*>(g_tab);
        float4*       d2 = reinterpret_cast<float4*>(setab);
        const float4* s2 = reinterpret_cast<const float4*>(g_etab);
        for (int i = tid; i < (NV * NT) / 4; i += 256) { d1[i] = s1[i]; d2[i] = s2[i]; }
        for (int i = tid; i < NV / 4; i += 256)
            reinterpret_cast<float4*>(sroff)[i] = reinterpret_cast<const float4*>(g_roff)[i];
        for (int i = tid; i < (NT * NT) / 4; i += 256)
            reinterpret_cast<float4*>(strans)[i] = reinterpret_cast<const float4*>(trans)[i];
        if (tid < NT) { sst[tid] = st[tid]; setr[tid] = et[tid]; }
        const int4* sq = reinterpret_cast<const int4*>(seqs + blockIdx.x * 16 * NS);
        for (int i = tid; i < (16 * NS) / 4; i += 256)
            reinterpret_cast<int4*>(&sseq[0][0])[i] = sq[i];
    }
    __syncthreads();

    const int warp = tid >> 5;
    const int lane = tid & 31;
    const int slotA = 2 * warp, slotB = 2 * warp + 1;
    const int bA = blockIdx.x * 16 + slotA;
    const int bB = bA + 1;
    const int* seqA = sseq[slotA];
    const int* seqB = sseq[slotB];
    const bool act = lane < NT;
    const int  tc  = act ? lane : 0;      // clamped index for table reads

    // exp(transitions) column for this lane (one-time MUFU cost)
    float Ecol[NT];
#pragma unroll
    for (int p = 0; p < NT; p++) Ecol[p] = act ? __expf(strans[p * NT + tc]) : 0.0f;

    // numerators (gold path) + row-offset sums for both sequences
    float numA, numB;
    {
        const int* labA = labs + bA * NS;
        const int* labB = labs + bB * NS;
        float nA = 0.f, rA = 0.f, nB = 0.f, rB = 0.f;
        for (int s = lane; s < NS; s += 32) {
            int svA = seqA[s], lsA = labA[s];
            int svB = seqB[s], lsB = labB[s];
            nA += stab[svA * NT + lsA];  rA += sroff[svA];
            nB += stab[svB * NT + lsB];  rB += sroff[svB];
            if (s + 1 < NS) {
                nA += strans[lsA * NT + labA[s + 1]];
                nB += strans[lsB * NT + labB[s + 1]];
            }
        }
#pragma unroll
        for (int o = 16; o; o >>= 1) {
            nA += __shfl_xor_sync(0xffffffffu, nA, o);
            rA += __shfl_xor_sync(0xffffffffu, rA, o);
            nB += __shfl_xor_sync(0xffffffffu, nB, o);
            rB += __shfl_xor_sync(0xffffffffu, rB, o);
        }
        numA = nA + sst[labA[0]] + setr[labA[NS - 1]] - rA;   // roff folded in
        numB = nB + sst[labB[0]] + setr[labB[NS - 1]] - rB;
    }

    // scaled forward scan, two sequences interleaved
    float eS = act ? __expf(sst[tc]) : 0.0f;
    float pA = eS * setab[seqA[0] * NT + tc];
    float pB = eS * setab[seqB[0] * NT + tc];
    float cA = 0.0f, cB = 0.0f;
    pbuf[warp][0][0][lane] = pA;
    pbuf[warp][1][0][lane] = pB;
    __syncwarp();

#pragma unroll 1
    for (int s = 1; s < NS; s++) {
        const int par = s & 1;            // write buffer; read the other
        const int rb  = par ^ 1;
        // prefetch tokens + emissions (independent of alpha)
        int svA = seqA[s], svB = seqB[s];
        float eA = setab[svA * NT + tc];
        float eB = setab[svB * NT + tc];

        const float4* pa = reinterpret_cast<const float4*>(pbuf[warp][0][rb]);
        const float4* pb = reinterpret_cast<const float4*>(pbuf[warp][1][rb]);
        float4 ua0 = pa[0], ua1 = pa[1], ua2 = pa[2], ua3 = pa[3], ua4 = pa[4], ua5 = pa[5];
        float4 ub0 = pb[0], ub1 = pb[1], ub2 = pb[2], ub3 = pb[3], ub4 = pb[4], ub5 = pb[5];

        float xa0, xa1, xa2, xa3, xb0, xb1, xb2, xb3;
        xa0 = ua0.x * Ecol[0];  xa1 = ua0.y * Ecol[1];  xa2 = ua0.z * Ecol[2];  xa3 = ua0.w * Ecol[3];
        xb0 = ub0.x * Ecol[0];  xb1 = ub0.y * Ecol[1];  xb2 = ub0.z * Ecol[2];  xb3 = ub0.w * Ecol[3];
        xa0 = fmaf(ua1.x, Ecol[4],  xa0); xa1 = fmaf(ua1.y, Ecol[5],  xa1);
        xa2 = fmaf(ua1.z, Ecol[6],  xa2); xa3 = fmaf(ua1.w, Ecol[7],  xa3);
        xb0 = fmaf(ub1.x, Ecol[4],  xb0); xb1 = fmaf(ub1.y, Ecol[5],  xb1);
        xb2 = fmaf(ub1.z, Ecol[6],  xb2); xb3 = fmaf(ub1.w, Ecol[7],  xb3);
        xa0 = fmaf(ua2.x, Ecol[8],  xa0); xa1 = fmaf(ua2.y, Ecol[9],  xa1);
        xa2 = fmaf(ua2.z, Ecol[10], xa2); xa3 = fmaf(ua2.w, Ecol[11], xa3);
        xb0 = fmaf(ub2.x, Ecol[8],  xb0); xb1 = fmaf(ub2.y, Ecol[9],  xb1);
        xb2 = fmaf(ub2.z, Ecol[10], xb2); xb3 = fmaf(ub2.w, Ecol[11], xb3);
        xa0 = fmaf(ua3.x, Ecol[12], xa0); xa1 = fmaf(ua3.y, Ecol[13], xa1);
        xa2 = fmaf(ua3.z, Ecol[14], xa2); xa3 = fmaf(ua3.w, Ecol[15], xa3);
        xb0 = fmaf(ub3.x, Ecol[12], xb0); xb1 = fmaf(ub3.y, Ecol[13], xb1);
        xb2 = fmaf(ub3.z, Ecol[14], xb2); xb3 = fmaf(ub3.w, Ecol[15], xb3);
        xa0 = fmaf(ua4.x, Ecol[16], xa0); xa1 = fmaf(ua4.y, Ecol[17], xa1);
        xa2 = fmaf(ua4.z, Ecol[18], xa2); xa3 = fmaf(ua4.w, Ecol[19], xa3);
        xb0 = fmaf(ub4.x, Ecol[16], xb0); xb1 = fmaf(ub4.y, Ecol[17], xb1);
        xb2 = fmaf(ub4.z, Ecol[18], xb2); xb3 = fmaf(ub4.w, Ecol[19], xb3);
        xa0 = fmaf(ua5.x, Ecol[20], xa0); xa1 = fmaf(ua5.y, Ecol[21], xa1);
        xa2 = fmaf(ua5.z, Ecol[22], xa2); xa3 = fmaf(ua5.w, Ecol[23], xa3);
        xb0 = fmaf(ub5.x, Ecol[20], xb0); xb1 = fmaf(ub5.y, Ecol[21], xb1);
        xb2 = fmaf(ub5.z, Ecol[22], xb2); xb3 = fmaf(ub5.w, Ecol[23], xb3);

        pA = ((xa0 + xa1) + (xa2 + xa3)) * eA;
        pB = ((xb0 + xb1) + (xb2 + xb3)) * eB;

        if ((s & 7) == 0) {               // renormalize every 8 steps
            float sA0 = ((ua0.x + ua0.y) + (ua0.z + ua0.w)) + ((ua1.x + ua1.y) + (ua1.z + ua1.w));
            float sA1 = ((ua2.x + ua2.y) + (ua2.z + ua2.w)) + ((ua3.x + ua3.y) + (ua3.z + ua3.w));
            float sA2 = ((ua4.x + ua4.y) + (ua4.z + ua4.w)) + ((ua5.x + ua5.y) + (ua5.z + ua5.w));
            float sB0 = ((ub0.x + ub0.y) + (ub0.z + ub0.w)) + ((ub1.x + ub1.y) + (ub1.z + ub1.w));
            float sB1 = ((ub2.x + ub2.y) + (ub2.z + ub2.w)) + ((ub3.x + ub3.y) + (ub3.z + ub3.w));
            float sB2 = ((ub4.x + ub4.y) + (ub4.z + ub4.w)) + ((ub5.x + ub5.y) + (ub5.z + ub5.w));
            float ssA = sA0 + sA1 + sA2;
            float ssB = sB0 + sB1 + sB2;
            pA *= __fdividef(1.0f, ssA);
            pB *= __fdividef(1.0f, ssB);
            cA += __logf(ssA);
            cB += __logf(ssB);
        }
        pbuf[warp][0][par][lane] = pA;
        pbuf[warp][1][par][lane] = pB;
        __syncwarp();
    }

    // denom_part = c + log( sum_t p[t]*exp(end[t]) )  (roff already in num)
    float ee = act ? __expf(setr[tc]) : 0.0f;
    float vA = pA * ee, vB = pB * ee;
#pragma unroll
    for (int o = 16; o; o >>= 1) {
        vA += __shfl_xor_sync(0xffffffffu, vA, o);
        vB += __shfl_xor_sync(0xffffffffu, vB, o);
    }
    if (lane == 0) {
        sll[slotA] = numA - (cA + __logf(vA));
        sll[slotB] = numB - (cB + __logf(vB));
    }
    __syncthreads();

    // fused deterministic reduce: int64 fixed-point atomics + last-block write
    if (tid == 0) {
        float bs = 0.0f;
#pragma unroll
        for (int w = 0; w < 16; w++) bs += sll[w];
        long long q = __float2ll_rn(bs * FPSCALE);
        atomicAdd(&g_acc, (unsigned long long)q);
        __threadfence();
        unsigned int done = atomicAdd(&g_ticket, 1u);
        if (done == gridDim.x - 1) {
            unsigned long long tot = atomicAdd(&g_acc, 0ULL);   // safe read
            double mean = (double)(long long)tot / ((double)FPSCALE * (double)NB);
            out[0] = (float)(-mean);
        }
    }
}

// ---------------------------------------------------------------------------
extern "C" void kernel_launch(void* const* d_in, const int* in_sizes, int n_in,
                              void* d_out, int out_size) {
    const int*   sequences   = (const int*)  d_in[0];
    const int*   labels      = (const int*)  d_in[1];
    // d_in[2] = true_lengths (unused by the reference forward)
    const float* emb         = (const float*)d_in[3];
    const float* w1          = (const float*)d_in[4];
    const float* b1          = (const float*)d_in[5];
    const float* w2          = (const float*)d_in[6];
    const float* b2          = (const float*)d_in[7];
    const float* start_trans = (const float*)d_in[8];
    const float* end_trans   = (const float*)d_in[9];
    const float* transitions = (const float*)d_in[10];
    float* out = (float*)d_out;

    k_transpose<<<dim3(16, 16), dim3(32, 8)>>>(w1);
    k_hidden<<<dim3(NV / 8, KC), 128>>>(emb);
    k_scores<<<NV, NT * 32>>>(b1, w2, b2);
    k_crf<<<NB / 16, 256>>>(sequences, labels, start_trans, end_trans, transitions, out);
}